// round 1
// baseline (speedup 1.0000x reference)
#include <cuda_runtime.h>
#include <cfloat>

// Problem constants
#define B_  4
#define L_  2048
#define D_  1024
#define H_  16
#define HD_ 64
#define M_TOT (B_ * L_)   // 8192

// Scratch (allocation-free rule: __device__ globals)
__device__ float g_q[B_ * L_ * D_];    // [B,H,L,HD] head-major
__device__ float g_k[B_ * L_ * D_];
__device__ float g_v[B_ * L_ * D_];
__device__ float g_ctx[B_ * L_ * D_];  // [B,L,D]

// ---------------------------------------------------------------------------
// GEMM (NT): C[m,n] = sum_k A[m,k] * W[n,k]   (x @ W.T, Linear semantics)
// A: [M,K] row-major, W: [N,K] row-major.
// MODE 0: C row-major [M,N]
// MODE 1: scatter to head-major [B,H,L,HD]: m=(b,l), n=(h,hd)
// 128x128x8 tiles, 256 threads, 8x8 micro-tile per thread.
// ---------------------------------------------------------------------------
template <int MODE>
__global__ __launch_bounds__(256) void gemm_nt(
    const float* __restrict__ A, const float* __restrict__ W,
    float* __restrict__ C, int M, int N, int Kd)
{
    __shared__ float As[8][132];  // [k][m], padded vs store conflicts
    __shared__ float Ws[8][132];  // [k][n]

    const int tid  = threadIdx.x;
    const int trow = tid >> 4;    // 0..15
    const int tcol = tid & 15;    // 0..15
    const int rowBase = blockIdx.y * 128;
    const int colBase = blockIdx.x * 128;

    const int lr = tid >> 1;         // 0..127 (tile row for loads)
    const int ls = (tid & 1) << 2;   // 0 or 4 (k sub-offset)

    float acc[8][8];
#pragma unroll
    for (int i = 0; i < 8; i++)
#pragma unroll
        for (int j = 0; j < 8; j++) acc[i][j] = 0.f;

    const float* Arow = A + (size_t)(rowBase + lr) * Kd + ls;
    const float* Wrow = W + (size_t)(colBase + lr) * Kd + ls;

    for (int k0 = 0; k0 < Kd; k0 += 8) {
        const float4 av = *(const float4*)(Arow + k0);
        const float4 wv = *(const float4*)(Wrow + k0);
        __syncthreads();   // previous iteration's smem reads complete
        As[ls + 0][lr] = av.x; As[ls + 1][lr] = av.y;
        As[ls + 2][lr] = av.z; As[ls + 3][lr] = av.w;
        Ws[ls + 0][lr] = wv.x; Ws[ls + 1][lr] = wv.y;
        Ws[ls + 2][lr] = wv.z; Ws[ls + 3][lr] = wv.w;
        __syncthreads();
#pragma unroll
        for (int kk = 0; kk < 8; kk++) {
            float af[8], wf[8];
            *(float4*)(af)     = *(const float4*)&As[kk][trow * 8];
            *(float4*)(af + 4) = *(const float4*)&As[kk][trow * 8 + 4];
            *(float4*)(wf)     = *(const float4*)&Ws[kk][tcol * 8];
            *(float4*)(wf + 4) = *(const float4*)&Ws[kk][tcol * 8 + 4];
#pragma unroll
            for (int i = 0; i < 8; i++)
#pragma unroll
                for (int j = 0; j < 8; j++)
                    acc[i][j] = fmaf(af[i], wf[j], acc[i][j]);
        }
    }

#pragma unroll
    for (int i = 0; i < 8; i++) {
        const int m = rowBase + trow * 8 + i;
        const int n = colBase + tcol * 8;
        float4 lo = make_float4(acc[i][0], acc[i][1], acc[i][2], acc[i][3]);
        float4 hi = make_float4(acc[i][4], acc[i][5], acc[i][6], acc[i][7]);
        if (MODE == 0) {
            float* dst = &C[(size_t)m * N + n];
            *(float4*)(dst)     = lo;
            *(float4*)(dst + 4) = hi;
        } else {
            // m = b*L + l ; n = h*HD + hd. tcol*8 is 8-aligned so all 8 cols
            // share one h (HD=64 divisible by 8).
            const int b  = m >> 11;          // /L_
            const int l  = m & (L_ - 1);
            const int h  = n >> 6;           // /HD_
            const int hd = n & (HD_ - 1);
            float* dst = &C[(((size_t)(b * H_ + h)) * L_ + l) * HD_ + hd];
            *(float4*)(dst)     = lo;
            *(float4*)(dst + 4) = hi;
        }
    }
}

// ---------------------------------------------------------------------------
// Flash attention over head-major Q/K/V ([B,H,L,HD], HD=64).
// Block = (q-tile of 64 rows) x (one b,h). 256 threads, 16x16 layout,
// each thread owns a 4x4 tile of the 64x64 score/output block.
// Online softmax; row stats reduced over the 16 threads sharing a row group
// via shfl_xor (lanes stay inside their 16-lane half-warp).
// Output written directly in [B,L,D] layout (context, pre-Wo).
// ---------------------------------------------------------------------------
__global__ __launch_bounds__(256) void attn_kernel(
    const float* __restrict__ Q, const float* __restrict__ K,
    const float* __restrict__ V, float* __restrict__ O)
{
    extern __shared__ float smem[];
    float* QsT = smem;              // [64 d][68] (d-major, value at [d*68 + row])
    float* KPs = smem + 64 * 68;    // K as [d][68]; reused as P [row][68]
    float* Vs  = smem + 2 * 64 * 68;// [c][68] row-major

    const int tid = threadIdx.x;
    const int tx  = tid & 15;       // score col group
    const int ty  = tid >> 4;       // score row group
    const int bh  = blockIdx.y;     // b*H + h
    const int q0  = blockIdx.x * 64;
    const size_t base = (size_t)bh * L_ * HD_;

    // Load Q tile, transposed to d-major, pre-scaled by 1/sqrt(HD)=0.125
    for (int idx = tid; idx < 64 * 16; idx += 256) {
        const int r  = idx >> 4;
        const int c4 = (idx & 15) << 2;
        const float4 v = *(const float4*)&Q[base + (size_t)(q0 + r) * HD_ + c4];
        QsT[(c4 + 0) * 68 + r] = v.x * 0.125f;
        QsT[(c4 + 1) * 68 + r] = v.y * 0.125f;
        QsT[(c4 + 2) * 68 + r] = v.z * 0.125f;
        QsT[(c4 + 3) * 68 + r] = v.w * 0.125f;
    }

    float m_i[4], l_i[4], acc[4][4];
#pragma unroll
    for (int i = 0; i < 4; i++) {
        m_i[i] = -FLT_MAX; l_i[i] = 0.f;
#pragma unroll
        for (int j = 0; j < 4; j++) acc[i][j] = 0.f;
    }

    for (int j0 = 0; j0 < L_; j0 += 64) {
        __syncthreads();  // prior P/V smem reads done before overwrite
        for (int idx = tid; idx < 64 * 16; idx += 256) {
            const int r  = idx >> 4;
            const int c4 = (idx & 15) << 2;
            const float4 kv = *(const float4*)&K[base + (size_t)(j0 + r) * HD_ + c4];
            KPs[(c4 + 0) * 68 + r] = kv.x;
            KPs[(c4 + 1) * 68 + r] = kv.y;
            KPs[(c4 + 2) * 68 + r] = kv.z;
            KPs[(c4 + 3) * 68 + r] = kv.w;
            const float4 vv = *(const float4*)&V[base + (size_t)(j0 + r) * HD_ + c4];
            *(float4*)&Vs[r * 68 + c4] = vv;
        }
        __syncthreads();

        // S = Q K^T (64x64), each thread 4x4
        float s[4][4];
#pragma unroll
        for (int i = 0; i < 4; i++)
#pragma unroll
            for (int j = 0; j < 4; j++) s[i][j] = 0.f;
#pragma unroll 8
        for (int d = 0; d < 64; d++) {
            float qf[4], kf[4];
#pragma unroll
            for (int i = 0; i < 4; i++) qf[i] = QsT[d * 68 + ty * 4 + i];
#pragma unroll
            for (int j = 0; j < 4; j++) kf[j] = KPs[d * 68 + tx * 4 + j];
#pragma unroll
            for (int i = 0; i < 4; i++)
#pragma unroll
                for (int j = 0; j < 4; j++)
                    s[i][j] = fmaf(qf[i], kf[j], s[i][j]);
        }

        // online softmax update (row stats shared across the 16-lane group)
        float p[4][4];
#pragma unroll
        for (int i = 0; i < 4; i++) {
            float rm = fmaxf(fmaxf(s[i][0], s[i][1]), fmaxf(s[i][2], s[i][3]));
#pragma unroll
            for (int off = 8; off >= 1; off >>= 1)
                rm = fmaxf(rm, __shfl_xor_sync(0xffffffffu, rm, off));
            const float nm   = fmaxf(m_i[i], rm);
            const float corr = __expf(m_i[i] - nm);
            float rs = 0.f;
#pragma unroll
            for (int j = 0; j < 4; j++) {
                p[i][j] = __expf(s[i][j] - nm);
                rs += p[i][j];
            }
#pragma unroll
            for (int off = 8; off >= 1; off >>= 1)
                rs += __shfl_xor_sync(0xffffffffu, rs, off);
            l_i[i] = l_i[i] * corr + rs;
            m_i[i] = nm;
#pragma unroll
            for (int j = 0; j < 4; j++) acc[i][j] *= corr;
        }

        __syncthreads();  // all K reads from KPs done
#pragma unroll
        for (int i = 0; i < 4; i++)
#pragma unroll
            for (int j = 0; j < 4; j++)
                KPs[(ty * 4 + i) * 68 + tx * 4 + j] = p[i][j];
        __syncthreads();

        // O += P V  (64x64x64)
#pragma unroll 8
        for (int c = 0; c < 64; c++) {
            float pf[4], vf[4];
#pragma unroll
            for (int i = 0; i < 4; i++) pf[i] = KPs[(ty * 4 + i) * 68 + c];
#pragma unroll
            for (int j = 0; j < 4; j++) vf[j] = Vs[c * 68 + tx * 4 + j];
#pragma unroll
            for (int i = 0; i < 4; i++)
#pragma unroll
                for (int j = 0; j < 4; j++)
                    acc[i][j] = fmaf(pf[i], vf[j], acc[i][j]);
        }
    }

    // epilogue: normalize and write ctx in [B, L, D] layout
    const int b = bh >> 4;
    const int h = bh & (H_ - 1);
#pragma unroll
    for (int i = 0; i < 4; i++) {
        const float inv = 1.0f / l_i[i];
        const int l = q0 + ty * 4 + i;
        float4 o = make_float4(acc[i][0] * inv, acc[i][1] * inv,
                               acc[i][2] * inv, acc[i][3] * inv);
        *(float4*)&O[((size_t)(b * L_ + l)) * D_ + h * HD_ + tx * 4] = o;
    }
}

// ---------------------------------------------------------------------------
extern "C" void kernel_launch(void* const* d_in, const int* in_sizes, int n_in,
                              void* d_out, int out_size)
{
    const float* queries = (const float*)d_in[0];
    const float* keys    = (const float*)d_in[1];
    const float* values  = (const float*)d_in[2];
    const float* Wq      = (const float*)d_in[3];
    const float* Wk      = (const float*)d_in[4];
    const float* Wv      = (const float*)d_in[5];
    const float* Wo      = (const float*)d_in[6];
    float* out = (float*)d_out;

    float *qp, *kp, *vp, *cp;
    cudaGetSymbolAddress((void**)&qp, g_q);
    cudaGetSymbolAddress((void**)&kp, g_k);
    cudaGetSymbolAddress((void**)&vp, g_v);
    cudaGetSymbolAddress((void**)&cp, g_ctx);

    // attention needs 3*64*68*4 = 52224 B dynamic smem (> default 48KB)
    const int smem_attn = 3 * 64 * 68 * (int)sizeof(float);
    cudaFuncSetAttribute(attn_kernel,
                         cudaFuncAttributeMaxDynamicSharedMemorySize, smem_attn);

    const dim3 gemm_grid(D_ / 128, M_TOT / 128);  // (8, 64)
    gemm_nt<1><<<gemm_grid, 256>>>(queries, Wq, qp, M_TOT, D_, D_);
    gemm_nt<1><<<gemm_grid, 256>>>(keys,    Wk, kp, M_TOT, D_, D_);
    gemm_nt<1><<<gemm_grid, 256>>>(values,  Wv, vp, M_TOT, D_, D_);

    const dim3 attn_grid(L_ / 64, B_ * H_);       // (32, 64)
    attn_kernel<<<attn_grid, 256, smem_attn>>>(qp, kp, vp, cp);

    gemm_nt<0><<<gemm_grid, 256>>>(cp, Wo, out, M_TOT, D_, D_);
}

// round 2
// speedup vs baseline: 3.0324x; 3.0324x over previous
#include <cuda_runtime.h>
#include <cfloat>

// Problem constants
#define B_  4
#define L_  2048
#define D_  1024
#define H_  16
#define HD_ 64
#define M_TOT (B_ * L_)   // 8192

// Scratch (allocation-free rule: __device__ globals)
__device__ float g_q[B_ * L_ * D_];    // [B,H,L,HD] head-major
__device__ float g_k[B_ * L_ * D_];
__device__ float g_v[B_ * L_ * D_];
__device__ float g_ctx[B_ * L_ * D_];  // [B,L,D]

// ---------------------------------------------------------------------------
// helpers
// ---------------------------------------------------------------------------
__device__ __forceinline__ unsigned f2tf(float x) {
    unsigned u;
    asm("cvt.rna.tf32.f32 %0, %1;" : "=r"(u) : "f"(x));
    return u;
}

// D(16x8) += A(16x8) * B(8x8), tf32, A row-major frag, B col-major frag
__device__ __forceinline__ void mma8(float* d, const unsigned* a,
                                     unsigned b0, unsigned b1) {
    asm volatile(
        "mma.sync.aligned.m16n8k8.row.col.f32.tf32.tf32.f32 "
        "{%0,%1,%2,%3}, {%4,%5,%6,%7}, {%8,%9}, {%0,%1,%2,%3};\n"
        : "+f"(d[0]), "+f"(d[1]), "+f"(d[2]), "+f"(d[3])
        : "r"(a[0]), "r"(a[1]), "r"(a[2]), "r"(a[3]), "r"(b0), "r"(b1));
}

// ---------------------------------------------------------------------------
// tf32 GEMM (NT): C[m,n] = sum_k A[m,k] * W[n,k]
// M=8192, N=K=1024. CTA 128x128, kTile=16. 256 thr = 8 warps (2m x 4n),
// warp tile m64 x n32 = 4x4 mma tiles.
// MODE 0: C row-major [M,1024]; MODE 1: scatter head-major [B,H,L,HD].
// ---------------------------------------------------------------------------
template <int MODE>
__global__ __launch_bounds__(256, 2) void gemm_tf32(
    const float* __restrict__ A, const float* __restrict__ W,
    float* __restrict__ C)
{
    __shared__ unsigned As[128 * 20];  // [row][k 16 + pad4]; pad20 -> 4g+t banks
    __shared__ unsigned Ws[128 * 20];

    const int tid  = threadIdx.x;
    const int lane = tid & 31;
    const int g    = lane >> 2;   // 0..7
    const int t    = lane & 3;    // 0..3
    const int w    = tid >> 5;    // 0..7
    const int wm   = (w & 1) * 64;
    const int wn   = (w >> 1) * 32;
    const int rowBase = blockIdx.y * 128;
    const int colBase = blockIdx.x * 128;

    const int lr = tid >> 2;        // 0..63 (load row; +64 second row)
    const int lc = (tid & 3) * 4;   // 0,4,8,12

    float acc[4][4][4];
#pragma unroll
    for (int i = 0; i < 4; i++)
#pragma unroll
        for (int j = 0; j < 4; j++)
#pragma unroll
            for (int c = 0; c < 4; c++) acc[i][j][c] = 0.f;

    const float* Ap = A + (size_t)(rowBase + lr) * D_ + lc;
    const float* Wp = W + (size_t)(colBase + lr) * D_ + lc;

    float4 ra0 = *(const float4*)(Ap);
    float4 ra1 = *(const float4*)(Ap + (size_t)64 * D_);
    float4 rw0 = *(const float4*)(Wp);
    float4 rw1 = *(const float4*)(Wp + (size_t)64 * D_);

    for (int k0 = 0; k0 < D_; k0 += 16) {
        __syncthreads();
        unsigned* as0 = &As[lr * 20 + lc];
        unsigned* as1 = &As[(lr + 64) * 20 + lc];
        unsigned* ws0 = &Ws[lr * 20 + lc];
        unsigned* ws1 = &Ws[(lr + 64) * 20 + lc];
        as0[0] = f2tf(ra0.x); as0[1] = f2tf(ra0.y); as0[2] = f2tf(ra0.z); as0[3] = f2tf(ra0.w);
        as1[0] = f2tf(ra1.x); as1[1] = f2tf(ra1.y); as1[2] = f2tf(ra1.z); as1[3] = f2tf(ra1.w);
        ws0[0] = f2tf(rw0.x); ws0[1] = f2tf(rw0.y); ws0[2] = f2tf(rw0.z); ws0[3] = f2tf(rw0.w);
        ws1[0] = f2tf(rw1.x); ws1[1] = f2tf(rw1.y); ws1[2] = f2tf(rw1.z); ws1[3] = f2tf(rw1.w);
        __syncthreads();

        if (k0 + 16 < D_) {
            const float* pa = Ap + k0 + 16;
            const float* pw = Wp + k0 + 16;
            ra0 = *(const float4*)(pa);
            ra1 = *(const float4*)(pa + (size_t)64 * D_);
            rw0 = *(const float4*)(pw);
            rw1 = *(const float4*)(pw + (size_t)64 * D_);
        }

#pragma unroll
        for (int kk = 0; kk < 16; kk += 8) {
            unsigned af[4][4], bf[4][2];
#pragma unroll
            for (int i = 0; i < 4; i++) {
                const int mb = wm + i * 16;
                af[i][0] = As[(mb + g) * 20 + kk + t];
                af[i][1] = As[(mb + g + 8) * 20 + kk + t];
                af[i][2] = As[(mb + g) * 20 + kk + t + 4];
                af[i][3] = As[(mb + g + 8) * 20 + kk + t + 4];
            }
#pragma unroll
            for (int j = 0; j < 4; j++) {
                const int nb = wn + j * 8 + g;
                bf[j][0] = Ws[nb * 20 + kk + t];
                bf[j][1] = Ws[nb * 20 + kk + t + 4];
            }
#pragma unroll
            for (int i = 0; i < 4; i++)
#pragma unroll
                for (int j = 0; j < 4; j++)
                    mma8(acc[i][j], af[i], bf[j][0], bf[j][1]);
        }
    }

    // epilogue: c0=[g][2t], c1=[g][2t+1], c2=[g+8][2t], c3=[g+8][2t+1]
#pragma unroll
    for (int i = 0; i < 4; i++) {
#pragma unroll
        for (int j = 0; j < 4; j++) {
            const int m  = rowBase + wm + i * 16 + g;
            const int n  = colBase + wn + j * 8 + 2 * t;
            float2 lo = make_float2(acc[i][j][0], acc[i][j][1]);
            float2 hi = make_float2(acc[i][j][2], acc[i][j][3]);
            if (MODE == 0) {
                *(float2*)&C[(size_t)m * 1024 + n]       = lo;
                *(float2*)&C[(size_t)(m + 8) * 1024 + n] = hi;
            } else {
                const int b  = m >> 11;
                const int l  = m & (L_ - 1);
                const int h  = n >> 6;
                const int hd = n & (HD_ - 1);
                float* dst = &C[(((size_t)(b * H_ + h)) * L_ + l) * HD_ + hd];
                *(float2*)dst                = lo;
                *(float2*)(dst + 8 * HD_)    = hi;   // row m+8, same (b,h)
            }
        }
    }
}

// ---------------------------------------------------------------------------
// tf32 flash attention. Block = 128 thr (4 warps), q-tile 64 (warp w owns
// rows w*16..+16, full n=64 -> softmax is warp-local via quad shuffles).
// Ks [64][68] (also used to stage Q), Ps [64][68], Vs [64][72] natural layout
// (V[c][hd] IS the col-major B fragment source: b0 = Vs[k0+t][n0+g]).
// ---------------------------------------------------------------------------
__global__ __launch_bounds__(128, 3) void attn_tf32(
    const float* __restrict__ Q, const float* __restrict__ K,
    const float* __restrict__ V, float* __restrict__ O)
{
    extern __shared__ unsigned sm[];
    unsigned* Ks = sm;                 // [64][68]
    unsigned* Ps = sm + 64 * 68;       // [64][68]
    unsigned* Vs = sm + 2 * 64 * 68;   // [64][72]

    const int tid  = threadIdx.x;
    const int lane = tid & 31;
    const int g    = lane >> 2;
    const int t    = lane & 3;
    const int w    = tid >> 5;
    const int m0   = w * 16;
    const int bh   = blockIdx.y;
    const int q0   = blockIdx.x * 64;
    const size_t base = (size_t)bh * (L_ * HD_);

    // ---- stage Q (scaled by 1/8) into Ks, then preload Q fragments ----
#pragma unroll
    for (int i = 0; i < 8; i++) {
        const int f  = i * 128 + tid;
        const int r  = f >> 4;
        const int c4 = (f & 15) << 2;
        const float4 v = *(const float4*)&Q[base + (size_t)(q0 + r) * HD_ + c4];
        unsigned* d = &Ks[r * 68 + c4];
        d[0] = f2tf(v.x * 0.125f); d[1] = f2tf(v.y * 0.125f);
        d[2] = f2tf(v.z * 0.125f); d[3] = f2tf(v.w * 0.125f);
    }
    __syncthreads();

    unsigned qf[8][4];
#pragma unroll
    for (int ks = 0; ks < 8; ks++) {
        qf[ks][0] = Ks[(m0 + g) * 68 + ks * 8 + t];
        qf[ks][1] = Ks[(m0 + g + 8) * 68 + ks * 8 + t];
        qf[ks][2] = Ks[(m0 + g) * 68 + ks * 8 + t + 4];
        qf[ks][3] = Ks[(m0 + g + 8) * 68 + ks * 8 + t + 4];
    }

    float oacc[8][4];
#pragma unroll
    for (int j = 0; j < 8; j++)
#pragma unroll
        for (int c = 0; c < 4; c++) oacc[j][c] = 0.f;
    float mr0 = -FLT_MAX, mr1 = -FLT_MAX, l0 = 0.f, l1 = 0.f;

    for (int j0 = 0; j0 < L_; j0 += 64) {
        __syncthreads();  // everyone done with previous Ks/Vs
#pragma unroll
        for (int i = 0; i < 8; i++) {
            const int f  = i * 128 + tid;
            const int r  = f >> 4;
            const int c4 = (f & 15) << 2;
            const float4 kv = *(const float4*)&K[base + (size_t)(j0 + r) * HD_ + c4];
            unsigned* dk = &Ks[r * 68 + c4];
            dk[0] = f2tf(kv.x); dk[1] = f2tf(kv.y); dk[2] = f2tf(kv.z); dk[3] = f2tf(kv.w);
            const float4 vv = *(const float4*)&V[base + (size_t)(j0 + r) * HD_ + c4];
            unsigned* dv = &Vs[r * 72 + c4];
            dv[0] = f2tf(vv.x); dv[1] = f2tf(vv.y); dv[2] = f2tf(vv.z); dv[3] = f2tf(vv.w);
        }
        __syncthreads();

        // ---- S = Q K^T (m16 x n64 per warp) ----
        float sacc[8][4];
#pragma unroll
        for (int j = 0; j < 8; j++)
#pragma unroll
            for (int c = 0; c < 4; c++) sacc[j][c] = 0.f;
#pragma unroll
        for (int ks = 0; ks < 8; ks++) {
#pragma unroll
            for (int j = 0; j < 8; j++) {
                const unsigned b0 = Ks[(j * 8 + g) * 68 + ks * 8 + t];
                const unsigned b1 = Ks[(j * 8 + g) * 68 + ks * 8 + t + 4];
                mma8(sacc[j], qf[ks], b0, b1);
            }
        }

        // ---- online softmax (rows g and g+8; quad = lanes sharing g) ----
        float rm0 = -FLT_MAX, rm1 = -FLT_MAX;
#pragma unroll
        for (int j = 0; j < 8; j++) {
            rm0 = fmaxf(rm0, fmaxf(sacc[j][0], sacc[j][1]));
            rm1 = fmaxf(rm1, fmaxf(sacc[j][2], sacc[j][3]));
        }
        rm0 = fmaxf(rm0, __shfl_xor_sync(0xffffffffu, rm0, 1));
        rm0 = fmaxf(rm0, __shfl_xor_sync(0xffffffffu, rm0, 2));
        rm1 = fmaxf(rm1, __shfl_xor_sync(0xffffffffu, rm1, 1));
        rm1 = fmaxf(rm1, __shfl_xor_sync(0xffffffffu, rm1, 2));

        const float nm0 = fmaxf(mr0, rm0);
        const float nm1 = fmaxf(mr1, rm1);
        const float cor0 = __expf(mr0 - nm0);
        const float cor1 = __expf(mr1 - nm1);
        mr0 = nm0; mr1 = nm1;

        float rs0 = 0.f, rs1 = 0.f;
#pragma unroll
        for (int j = 0; j < 8; j++) {
            const float p0 = __expf(sacc[j][0] - nm0);
            const float p1 = __expf(sacc[j][1] - nm0);
            const float p2 = __expf(sacc[j][2] - nm1);
            const float p3 = __expf(sacc[j][3] - nm1);
            rs0 += p0 + p1;
            rs1 += p2 + p3;
            unsigned* pr0 = &Ps[(m0 + g) * 68 + j * 8 + 2 * t];
            unsigned* pr1 = &Ps[(m0 + g + 8) * 68 + j * 8 + 2 * t];
            pr0[0] = f2tf(p0); pr0[1] = f2tf(p1);
            pr1[0] = f2tf(p2); pr1[1] = f2tf(p3);
            oacc[j][0] *= cor0; oacc[j][1] *= cor0;
            oacc[j][2] *= cor1; oacc[j][3] *= cor1;
        }
        rs0 += __shfl_xor_sync(0xffffffffu, rs0, 1);
        rs0 += __shfl_xor_sync(0xffffffffu, rs0, 2);
        rs1 += __shfl_xor_sync(0xffffffffu, rs1, 1);
        rs1 += __shfl_xor_sync(0xffffffffu, rs1, 2);
        l0 = l0 * cor0 + rs0;
        l1 = l1 * cor1 + rs1;

        __syncwarp();  // P stores visible to this warp's loads

        // ---- O += P V (m16 x n64, k=64) ----
#pragma unroll
        for (int ks = 0; ks < 8; ks++) {
            unsigned pa[4];
            pa[0] = Ps[(m0 + g) * 68 + ks * 8 + t];
            pa[1] = Ps[(m0 + g + 8) * 68 + ks * 8 + t];
            pa[2] = Ps[(m0 + g) * 68 + ks * 8 + t + 4];
            pa[3] = Ps[(m0 + g + 8) * 68 + ks * 8 + t + 4];
#pragma unroll
            for (int j = 0; j < 8; j++) {
                const unsigned b0 = Vs[(ks * 8 + t) * 72 + j * 8 + g];
                const unsigned b1 = Vs[(ks * 8 + t + 4) * 72 + j * 8 + g];
                mma8(oacc[j], pa, b0, b1);
            }
        }
    }

    // ---- epilogue: normalize, write ctx [B,L,D] ----
    const int b = bh >> 4;
    const int h = bh & (H_ - 1);
    const float inv0 = 1.0f / l0;
    const float inv1 = 1.0f / l1;
    const int r0 = q0 + m0 + g;
    const int r1 = r0 + 8;
#pragma unroll
    for (int j = 0; j < 8; j++) {
        const int col = h * HD_ + j * 8 + 2 * t;
        *(float2*)&O[((size_t)(b * L_ + r0)) * D_ + col] =
            make_float2(oacc[j][0] * inv0, oacc[j][1] * inv0);
        *(float2*)&O[((size_t)(b * L_ + r1)) * D_ + col] =
            make_float2(oacc[j][2] * inv1, oacc[j][3] * inv1);
    }
}

// ---------------------------------------------------------------------------
extern "C" void kernel_launch(void* const* d_in, const int* in_sizes, int n_in,
                              void* d_out, int out_size)
{
    const float* queries = (const float*)d_in[0];
    const float* keys    = (const float*)d_in[1];
    const float* values  = (const float*)d_in[2];
    const float* Wq      = (const float*)d_in[3];
    const float* Wk      = (const float*)d_in[4];
    const float* Wv      = (const float*)d_in[5];
    const float* Wo      = (const float*)d_in[6];
    float* out = (float*)d_out;

    float *qp, *kp, *vp, *cp;
    cudaGetSymbolAddress((void**)&qp, g_q);
    cudaGetSymbolAddress((void**)&kp, g_k);
    cudaGetSymbolAddress((void**)&vp, g_v);
    cudaGetSymbolAddress((void**)&cp, g_ctx);

    const int smem_attn = (2 * 64 * 68 + 64 * 72) * (int)sizeof(unsigned);  // 53248
    cudaFuncSetAttribute(attn_tf32,
                         cudaFuncAttributeMaxDynamicSharedMemorySize, smem_attn);

    const dim3 gemm_grid(D_ / 128, M_TOT / 128);  // (8, 64)
    gemm_tf32<1><<<gemm_grid, 256>>>(queries, Wq, qp);
    gemm_tf32<1><<<gemm_grid, 256>>>(keys,    Wk, kp);
    gemm_tf32<1><<<gemm_grid, 256>>>(values,  Wv, vp);

    const dim3 attn_grid(L_ / 64, B_ * H_);       // (32, 64)
    attn_tf32<<<attn_grid, 128, smem_attn>>>(qp, kp, vp, cp);

    gemm_tf32<0><<<gemm_grid, 256>>>(cp, Wo, out);
}